// round 9
// baseline (speedup 1.0000x reference)
#include <cuda_runtime.h>
#include <math.h>

// Problem constants
#define LATENT   128
#define HIDDEN   2048
#define NPARTS   128
#define KCOLS    2048
#define OMEGA_D  (9 * NPARTS)   // 1152
#define TRANZ_D  (3 * NPARTS)   // 384

// Scratch: ping-pong activation buffers (16.8 MB each) — static, no allocation.
__device__ float g_buf0[HIDDEN * KCOLS];
__device__ float g_buf1[HIDDEN * KCOLS];

// ----------------------------------------------------------------------------
// Tiled fp32 GEMM: C = (relu?)(A @ B)
//   A: (M, Kin) row-major (weights)
//   B: (Kin, N) row-major (activations, N = 2048)
//   C: (M, N)   row-major
// BM=BN=128, BK=16, 256 threads, 8x8 per thread, register double-buffered loads.
// All dims are multiples of the tile sizes for this problem -> no bounds checks.
// ----------------------------------------------------------------------------
template <int DO_RELU>
__global__ __launch_bounds__(256, 2)
void gemm128_kernel(const float* __restrict__ A, const float* __restrict__ B,
                    float* __restrict__ C, int M, int N, int Kin)
{
    constexpr int BM = 128, BN = 128, BK = 16;
    __shared__ float As[BK][BM + 4];   // +4 pad: reduce store conflicts, keep float4 align
    __shared__ float Bs[BK][BN];

    const int tid = threadIdx.x;
    const int bm = blockIdx.y * BM;
    const int bn = blockIdx.x * BN;

    const int tm8 = (tid >> 4) * 8;    // 0..120, output row group within tile
    const int tn8 = (tid & 15) * 8;    // 0..120, output col group within tile

    // A tile loads: 128 rows x 16 k, float4 along k. Each thread: 2 float4.
    const int a_row = tid >> 2;        // 0..63
    const int a_k4  = (tid & 3) * 4;   // 0,4,8,12
    // B tile loads: 16 rows x 128 cols, float4 along n. Each thread: 2 float4.
    const int b_row = tid >> 5;        // 0..7
    const int b_c4  = (tid & 31) * 4;  // 0..124

    const float* Aptr = A + (size_t)(bm + a_row) * Kin + a_k4;
    const float* Bptr = B + (size_t)b_row * N + bn + b_c4;

    float4 a0 = *(const float4*)(Aptr);
    float4 a1 = *(const float4*)(Aptr + (size_t)64 * Kin);
    float4 b0 = *(const float4*)(Bptr);
    float4 b1 = *(const float4*)(Bptr + (size_t)8 * N);

    float acc[8][8];
    #pragma unroll
    for (int i = 0; i < 8; i++)
        #pragma unroll
        for (int j = 0; j < 8; j++) acc[i][j] = 0.0f;

    const int numT = Kin / BK;
    for (int t = 0; t < numT; ++t) {
        // Stage current tile into shared memory
        As[a_k4 + 0][a_row] = a0.x;
        As[a_k4 + 1][a_row] = a0.y;
        As[a_k4 + 2][a_row] = a0.z;
        As[a_k4 + 3][a_row] = a0.w;
        As[a_k4 + 0][a_row + 64] = a1.x;
        As[a_k4 + 1][a_row + 64] = a1.y;
        As[a_k4 + 2][a_row + 64] = a1.z;
        As[a_k4 + 3][a_row + 64] = a1.w;
        *(float4*)&Bs[b_row][b_c4]     = b0;
        *(float4*)&Bs[b_row + 8][b_c4] = b1;
        __syncthreads();

        // Prefetch next tile into registers (overlaps with compute below)
        if (t + 1 < numT) {
            const float* Ap = Aptr + (size_t)(t + 1) * BK;
            a0 = *(const float4*)(Ap);
            a1 = *(const float4*)(Ap + (size_t)64 * Kin);
            const float* Bp = Bptr + (size_t)(t + 1) * BK * N;
            b0 = *(const float4*)(Bp);
            b1 = *(const float4*)(Bp + (size_t)8 * N);
        }

        #pragma unroll
        for (int kk = 0; kk < BK; kk++) {
            float4 av0 = *(const float4*)&As[kk][tm8];
            float4 av1 = *(const float4*)&As[kk][tm8 + 4];
            float4 bv0 = *(const float4*)&Bs[kk][tn8];
            float4 bv1 = *(const float4*)&Bs[kk][tn8 + 4];
            float am[8] = {av0.x, av0.y, av0.z, av0.w, av1.x, av1.y, av1.z, av1.w};
            float bb[8] = {bv0.x, bv0.y, bv0.z, bv0.w, bv1.x, bv1.y, bv1.z, bv1.w};
            #pragma unroll
            for (int i = 0; i < 8; i++)
                #pragma unroll
                for (int j = 0; j < 8; j++)
                    acc[i][j] = fmaf(am[i], bb[j], acc[i][j]);
        }
        __syncthreads();
    }

    // Epilogue: optional relu, float4 stores
    #pragma unroll
    for (int i = 0; i < 8; i++) {
        float v[8];
        #pragma unroll
        for (int j = 0; j < 8; j++) {
            float x = acc[i][j];
            v[j] = DO_RELU ? fmaxf(x, 0.0f) : x;
        }
        size_t off = (size_t)(bm + tm8 + i) * N + bn + tn8;
        float4 o0 = make_float4(v[0], v[1], v[2], v[3]);
        float4 o1 = make_float4(v[4], v[5], v[6], v[7]);
        *(float4*)&C[off]     = o0;
        *(float4*)&C[off + 4] = o1;
    }
}

// ----------------------------------------------------------------------------
// 3x3 expm (scaling & squaring + 10-term Taylor) + output assembly.
// One thread per (part p, column k). Layouts (all row-major, K=2048 cols):
//   omega[(9p + 3r + c), k]  -> A[r][c]
//   rotations[(9p + i), k]   =  E[i]
//   transf[(12p + i), k]     =  E[i]            (i < 9)
//   transf[(12p + 9 + c), k] =  translations[(3p + c), k]
// ----------------------------------------------------------------------------
__device__ __forceinline__ void mat3mul(float* __restrict__ o,
                                        const float* __restrict__ a,
                                        const float* __restrict__ b)
{
    #pragma unroll
    for (int r = 0; r < 3; r++)
        #pragma unroll
        for (int c = 0; c < 3; c++)
            o[3 * r + c] = fmaf(a[3 * r + 0], b[c],
                           fmaf(a[3 * r + 1], b[3 + c],
                                a[3 * r + 2] * b[6 + c]));
}

__global__ void expm_assemble_kernel(const float* __restrict__ omega,
                                     const float* __restrict__ trans,
                                     float* __restrict__ rotations,
                                     float* __restrict__ transf)
{
    const int idx = blockIdx.x * blockDim.x + threadIdx.x;
    const int k = idx & (KCOLS - 1);
    const int p = idx >> 11;           // KCOLS = 2^11
    if (p >= NPARTS) return;

    float A[9];
    #pragma unroll
    for (int i = 0; i < 9; i++)
        A[i] = omega[(size_t)(9 * p + i) * KCOLS + k];

    // inf-norm
    float r0 = fabsf(A[0]) + fabsf(A[1]) + fabsf(A[2]);
    float r1 = fabsf(A[3]) + fabsf(A[4]) + fabsf(A[5]);
    float r2 = fabsf(A[6]) + fabsf(A[7]) + fabsf(A[8]);
    float nrm = fmaxf(r0, fmaxf(r1, r2));

    int s = 0;
    if (nrm > 0.25f) {
        s = (int)ceilf(log2f(nrm * 4.0f));
        if (s < 0) s = 0;
        if (s > 30) s = 30;
    }
    const float sc = exp2f((float)(-s));
    #pragma unroll
    for (int i = 0; i < 9; i++) A[i] *= sc;

    // E = I + A; T = A; Taylor terms 2..10 (||A|| <= 0.25 -> remainder ~6e-15)
    float E[9], T[9], Tn[9];
    #pragma unroll
    for (int i = 0; i < 9; i++) { E[i] = A[i]; T[i] = A[i]; }
    E[0] += 1.0f; E[4] += 1.0f; E[8] += 1.0f;

    #pragma unroll
    for (int term = 2; term <= 10; term++) {
        mat3mul(Tn, T, A);
        const float inv = 1.0f / (float)term;
        #pragma unroll
        for (int i = 0; i < 9; i++) {
            T[i] = Tn[i] * inv;
            E[i] += T[i];
        }
    }

    // squarings
    for (int q = 0; q < s; q++) {
        mat3mul(Tn, E, E);
        #pragma unroll
        for (int i = 0; i < 9; i++) E[i] = Tn[i];
    }

    // Write rotations + transf rotation rows
    #pragma unroll
    for (int i = 0; i < 9; i++) {
        rotations[(size_t)(9 * p + i) * KCOLS + k] = E[i];
        transf[(size_t)(12 * p + i) * KCOLS + k]   = E[i];
    }
    // Copy translation rows into transf
    #pragma unroll
    for (int c = 0; c < 3; c++) {
        float tv = trans[(size_t)(3 * p + c) * KCOLS + k];
        transf[(size_t)(12 * p + 9 + c) * KCOLS + k] = tv;
    }
}

// ----------------------------------------------------------------------------
// Launcher. Inputs (metadata order):
//   0: x_init (128,2048)  1: Wo0 (2048,128)  2: Wo1 (2048,2048)  3: Wo2 (2048,2048)
//   4: Wo3 (1152,2048)    5: Wt0 (2048,128)  6: Wt1 (2048,2048)  7: Wt2 (2048,2048)
//   8: Wt3 (384,2048)
// Output (flattened tuple): omega | transf | rotations | translations
// ----------------------------------------------------------------------------
extern "C" void kernel_launch(void* const* d_in, const int* in_sizes, int n_in,
                              void* d_out, int out_size)
{
    const float* x   = (const float*)d_in[0];
    const float* Wo0 = (const float*)d_in[1];
    const float* Wo1 = (const float*)d_in[2];
    const float* Wo2 = (const float*)d_in[3];
    const float* Wo3 = (const float*)d_in[4];
    const float* Wt0 = (const float*)d_in[5];
    const float* Wt1 = (const float*)d_in[6];
    const float* Wt2 = (const float*)d_in[7];
    const float* Wt3 = (const float*)d_in[8];

    float* out       = (float*)d_out;
    float* omega     = out;                                       // 1152*2048
    float* transf    = omega + (size_t)OMEGA_D * KCOLS;           // 1536*2048
    float* rotations = transf + (size_t)(12 * NPARTS) * KCOLS;    // 1152*2048
    float* trans     = rotations + (size_t)OMEGA_D * KCOLS;       // 384*2048

    float *buf0, *buf1;
    cudaGetSymbolAddress((void**)&buf0, g_buf0);
    cudaGetSymbolAddress((void**)&buf1, g_buf1);

    const dim3 blk(256);
    const dim3 gHH(KCOLS / 128, HIDDEN / 128);        // (16,16)
    const dim3 gOm(KCOLS / 128, OMEGA_D / 128);       // (16,9)
    const dim3 gTr(KCOLS / 128, TRANZ_D / 128);       // (16,3)

    // omega branch
    gemm128_kernel<1><<<gHH, blk>>>(Wo0, x,    buf0, HIDDEN,  KCOLS, LATENT);
    gemm128_kernel<1><<<gHH, blk>>>(Wo1, buf0, buf1, HIDDEN,  KCOLS, HIDDEN);
    gemm128_kernel<1><<<gHH, blk>>>(Wo2, buf1, buf0, HIDDEN,  KCOLS, HIDDEN);
    gemm128_kernel<0><<<gOm, blk>>>(Wo3, buf0, omega, OMEGA_D, KCOLS, HIDDEN);

    // translation branch
    gemm128_kernel<1><<<gHH, blk>>>(Wt0, x,    buf1, HIDDEN,  KCOLS, LATENT);
    gemm128_kernel<1><<<gHH, blk>>>(Wt1, buf1, buf0, HIDDEN,  KCOLS, HIDDEN);
    gemm128_kernel<1><<<gHH, blk>>>(Wt2, buf0, buf1, HIDDEN,  KCOLS, HIDDEN);
    gemm128_kernel<0><<<gTr, blk>>>(Wt3, buf1, trans, TRANZ_D, KCOLS, HIDDEN);

    // expm + output assembly
    const int total = NPARTS * KCOLS;                 // 262144 threads
    expm_assemble_kernel<<<total / 256, 256>>>(omega, trans, rotations, transf);
}

// round 12
// speedup vs baseline: 1.0000x; 1.0000x over previous
#include <cuda_runtime.h>
#include <math.h>

// Problem constants
#define LATENT   128
#define HIDDEN   2048
#define NPARTS   128
#define KCOLS    2048
#define OMEGA_D  (9 * NPARTS)   // 1152
#define TRANZ_D  (3 * NPARTS)   // 384

// Scratch: ping-pong activation buffers (16.8 MB each) — static, no allocation.
__device__ float g_buf0[HIDDEN * KCOLS];
__device__ float g_buf1[HIDDEN * KCOLS];

// ----------------------------------------------------------------------------
// Tiled fp32 GEMM: C = (relu?)(A @ B)
//   A: (M, Kin) row-major (weights)
//   B: (Kin, N) row-major (activations, N = 2048)
//   C: (M, N)   row-major
// BM=BN=128, BK=16, 256 threads, 8x8 per thread, register double-buffered loads.
// All dims are multiples of the tile sizes for this problem -> no bounds checks.
// ----------------------------------------------------------------------------
template <int DO_RELU>
__global__ __launch_bounds__(256, 2)
void gemm128_kernel(const float* __restrict__ A, const float* __restrict__ B,
                    float* __restrict__ C, int M, int N, int Kin)
{
    constexpr int BM = 128, BN = 128, BK = 16;
    __shared__ float As[BK][BM + 4];   // +4 pad: reduce store conflicts, keep float4 align
    __shared__ float Bs[BK][BN];

    const int tid = threadIdx.x;
    const int bm = blockIdx.y * BM;
    const int bn = blockIdx.x * BN;

    const int tm8 = (tid >> 4) * 8;    // 0..120, output row group within tile
    const int tn8 = (tid & 15) * 8;    // 0..120, output col group within tile

    // A tile loads: 128 rows x 16 k, float4 along k. Each thread: 2 float4.
    const int a_row = tid >> 2;        // 0..63
    const int a_k4  = (tid & 3) * 4;   // 0,4,8,12
    // B tile loads: 16 rows x 128 cols, float4 along n. Each thread: 2 float4.
    const int b_row = tid >> 5;        // 0..7
    const int b_c4  = (tid & 31) * 4;  // 0..124

    const float* Aptr = A + (size_t)(bm + a_row) * Kin + a_k4;
    const float* Bptr = B + (size_t)b_row * N + bn + b_c4;

    float4 a0 = *(const float4*)(Aptr);
    float4 a1 = *(const float4*)(Aptr + (size_t)64 * Kin);
    float4 b0 = *(const float4*)(Bptr);
    float4 b1 = *(const float4*)(Bptr + (size_t)8 * N);

    float acc[8][8];
    #pragma unroll
    for (int i = 0; i < 8; i++)
        #pragma unroll
        for (int j = 0; j < 8; j++) acc[i][j] = 0.0f;

    const int numT = Kin / BK;
    for (int t = 0; t < numT; ++t) {
        // Stage current tile into shared memory
        As[a_k4 + 0][a_row] = a0.x;
        As[a_k4 + 1][a_row] = a0.y;
        As[a_k4 + 2][a_row] = a0.z;
        As[a_k4 + 3][a_row] = a0.w;
        As[a_k4 + 0][a_row + 64] = a1.x;
        As[a_k4 + 1][a_row + 64] = a1.y;
        As[a_k4 + 2][a_row + 64] = a1.z;
        As[a_k4 + 3][a_row + 64] = a1.w;
        *(float4*)&Bs[b_row][b_c4]     = b0;
        *(float4*)&Bs[b_row + 8][b_c4] = b1;
        __syncthreads();

        // Prefetch next tile into registers (overlaps with compute below)
        if (t + 1 < numT) {
            const float* Ap = Aptr + (size_t)(t + 1) * BK;
            a0 = *(const float4*)(Ap);
            a1 = *(const float4*)(Ap + (size_t)64 * Kin);
            const float* Bp = Bptr + (size_t)(t + 1) * BK * N;
            b0 = *(const float4*)(Bp);
            b1 = *(const float4*)(Bp + (size_t)8 * N);
        }

        #pragma unroll
        for (int kk = 0; kk < BK; kk++) {
            float4 av0 = *(const float4*)&As[kk][tm8];
            float4 av1 = *(const float4*)&As[kk][tm8 + 4];
            float4 bv0 = *(const float4*)&Bs[kk][tn8];
            float4 bv1 = *(const float4*)&Bs[kk][tn8 + 4];
            float am[8] = {av0.x, av0.y, av0.z, av0.w, av1.x, av1.y, av1.z, av1.w};
            float bb[8] = {bv0.x, bv0.y, bv0.z, bv0.w, bv1.x, bv1.y, bv1.z, bv1.w};
            #pragma unroll
            for (int i = 0; i < 8; i++)
                #pragma unroll
                for (int j = 0; j < 8; j++)
                    acc[i][j] = fmaf(am[i], bb[j], acc[i][j]);
        }
        __syncthreads();
    }

    // Epilogue: optional relu, float4 stores
    #pragma unroll
    for (int i = 0; i < 8; i++) {
        float v[8];
        #pragma unroll
        for (int j = 0; j < 8; j++) {
            float x = acc[i][j];
            v[j] = DO_RELU ? fmaxf(x, 0.0f) : x;
        }
        size_t off = (size_t)(bm + tm8 + i) * N + bn + tn8;
        float4 o0 = make_float4(v[0], v[1], v[2], v[3]);
        float4 o1 = make_float4(v[4], v[5], v[6], v[7]);
        *(float4*)&C[off]     = o0;
        *(float4*)&C[off + 4] = o1;
    }
}

// ----------------------------------------------------------------------------
// 3x3 expm (scaling & squaring + 10-term Taylor) + output assembly.
// One thread per (part p, column k). Layouts (all row-major, K=2048 cols):
//   omega[(9p + 3r + c), k]  -> A[r][c]
//   rotations[(9p + i), k]   =  E[i]
//   transf[(12p + i), k]     =  E[i]            (i < 9)
//   transf[(12p + 9 + c), k] =  translations[(3p + c), k]
// ----------------------------------------------------------------------------
__device__ __forceinline__ void mat3mul(float* __restrict__ o,
                                        const float* __restrict__ a,
                                        const float* __restrict__ b)
{
    #pragma unroll
    for (int r = 0; r < 3; r++)
        #pragma unroll
        for (int c = 0; c < 3; c++)
            o[3 * r + c] = fmaf(a[3 * r + 0], b[c],
                           fmaf(a[3 * r + 1], b[3 + c],
                                a[3 * r + 2] * b[6 + c]));
}

__global__ void expm_assemble_kernel(const float* __restrict__ omega,
                                     const float* __restrict__ trans,
                                     float* __restrict__ rotations,
                                     float* __restrict__ transf)
{
    const int idx = blockIdx.x * blockDim.x + threadIdx.x;
    const int k = idx & (KCOLS - 1);
    const int p = idx >> 11;           // KCOLS = 2^11
    if (p >= NPARTS) return;

    float A[9];
    #pragma unroll
    for (int i = 0; i < 9; i++)
        A[i] = omega[(size_t)(9 * p + i) * KCOLS + k];

    // inf-norm
    float r0 = fabsf(A[0]) + fabsf(A[1]) + fabsf(A[2]);
    float r1 = fabsf(A[3]) + fabsf(A[4]) + fabsf(A[5]);
    float r2 = fabsf(A[6]) + fabsf(A[7]) + fabsf(A[8]);
    float nrm = fmaxf(r0, fmaxf(r1, r2));

    int s = 0;
    if (nrm > 0.25f) {
        s = (int)ceilf(log2f(nrm * 4.0f));
        if (s < 0) s = 0;
        if (s > 30) s = 30;
    }
    const float sc = exp2f((float)(-s));
    #pragma unroll
    for (int i = 0; i < 9; i++) A[i] *= sc;

    // E = I + A; T = A; Taylor terms 2..10 (||A|| <= 0.25 -> remainder ~6e-15)
    float E[9], T[9], Tn[9];
    #pragma unroll
    for (int i = 0; i < 9; i++) { E[i] = A[i]; T[i] = A[i]; }
    E[0] += 1.0f; E[4] += 1.0f; E[8] += 1.0f;

    #pragma unroll
    for (int term = 2; term <= 10; term++) {
        mat3mul(Tn, T, A);
        const float inv = 1.0f / (float)term;
        #pragma unroll
        for (int i = 0; i < 9; i++) {
            T[i] = Tn[i] * inv;
            E[i] += T[i];
        }
    }

    // squarings
    for (int q = 0; q < s; q++) {
        mat3mul(Tn, E, E);
        #pragma unroll
        for (int i = 0; i < 9; i++) E[i] = Tn[i];
    }

    // Write rotations + transf rotation rows
    #pragma unroll
    for (int i = 0; i < 9; i++) {
        rotations[(size_t)(9 * p + i) * KCOLS + k] = E[i];
        transf[(size_t)(12 * p + i) * KCOLS + k]   = E[i];
    }
    // Copy translation rows into transf
    #pragma unroll
    for (int c = 0; c < 3; c++) {
        float tv = trans[(size_t)(3 * p + c) * KCOLS + k];
        transf[(size_t)(12 * p + 9 + c) * KCOLS + k] = tv;
    }
}

// ----------------------------------------------------------------------------
// Launcher. Inputs (metadata order):
//   0: x_init (128,2048)  1: Wo0 (2048,128)  2: Wo1 (2048,2048)  3: Wo2 (2048,2048)
//   4: Wo3 (1152,2048)    5: Wt0 (2048,128)  6: Wt1 (2048,2048)  7: Wt2 (2048,2048)
//   8: Wt3 (384,2048)
// Output (flattened tuple): omega | transf | rotations | translations
// ----------------------------------------------------------------------------
extern "C" void kernel_launch(void* const* d_in, const int* in_sizes, int n_in,
                              void* d_out, int out_size)
{
    const float* x   = (const float*)d_in[0];
    const float* Wo0 = (const float*)d_in[1];
    const float* Wo1 = (const float*)d_in[2];
    const float* Wo2 = (const float*)d_in[3];
    const float* Wo3 = (const float*)d_in[4];
    const float* Wt0 = (const float*)d_in[5];
    const float* Wt1 = (const float*)d_in[6];
    const float* Wt2 = (const float*)d_in[7];
    const float* Wt3 = (const float*)d_in[8];

    float* out       = (float*)d_out;
    float* omega     = out;                                       // 1152*2048
    float* transf    = omega + (size_t)OMEGA_D * KCOLS;           // 1536*2048
    float* rotations = transf + (size_t)(12 * NPARTS) * KCOLS;    // 1152*2048
    float* trans     = rotations + (size_t)OMEGA_D * KCOLS;       // 384*2048

    float *buf0, *buf1;
    cudaGetSymbolAddress((void**)&buf0, g_buf0);
    cudaGetSymbolAddress((void**)&buf1, g_buf1);

    const dim3 blk(256);
    const dim3 gHH(KCOLS / 128, HIDDEN / 128);        // (16,16)
    const dim3 gOm(KCOLS / 128, OMEGA_D / 128);       // (16,9)
    const dim3 gTr(KCOLS / 128, TRANZ_D / 128);       // (16,3)

    // omega branch
    gemm128_kernel<1><<<gHH, blk>>>(Wo0, x,    buf0, HIDDEN,  KCOLS, LATENT);
    gemm128_kernel<1><<<gHH, blk>>>(Wo1, buf0, buf1, HIDDEN,  KCOLS, HIDDEN);
    gemm128_kernel<1><<<gHH, blk>>>(Wo2, buf1, buf0, HIDDEN,  KCOLS, HIDDEN);
    gemm128_kernel<0><<<gOm, blk>>>(Wo3, buf0, omega, OMEGA_D, KCOLS, HIDDEN);

    // translation branch
    gemm128_kernel<1><<<gHH, blk>>>(Wt0, x,    buf1, HIDDEN,  KCOLS, LATENT);
    gemm128_kernel<1><<<gHH, blk>>>(Wt1, buf1, buf0, HIDDEN,  KCOLS, HIDDEN);
    gemm128_kernel<1><<<gHH, blk>>>(Wt2, buf0, buf1, HIDDEN,  KCOLS, HIDDEN);
    gemm128_kernel<0><<<gTr, blk>>>(Wt3, buf1, trans, TRANZ_D, KCOLS, HIDDEN);

    // expm + output assembly
    const int total = NPARTS * KCOLS;                 // 262144 threads
    expm_assemble_kernel<<<total / 256, 256>>>(omega, trans, rotations, transf);
}

// round 13
// speedup vs baseline: 1.0030x; 1.0030x over previous
#include <cuda_runtime.h>
#include <math.h>

// Problem constants
#define LATENT   128
#define HIDDEN   2048
#define NPARTS   128
#define KCOLS    2048
#define OMEGA_D  (9 * NPARTS)   // 1152
#define TRANZ_D  (3 * NPARTS)   // 384

// Scratch: ping-pong activation buffers (16.8 MB each) — static, no allocation.
__device__ float g_buf0[HIDDEN * KCOLS];
__device__ float g_buf1[HIDDEN * KCOLS];

// ----------------------------------------------------------------------------
// Tiled fp32 GEMM: C = (relu?)(A @ B)
//   A: (M, Kin) row-major (weights)
//   B: (Kin, N) row-major (activations, N = 2048)
//   C: (M, N)   row-major
// BM=BN=128, BK=16, 256 threads, 8x8 per thread, register double-buffered loads.
// All dims are multiples of the tile sizes for this problem -> no bounds checks.
// ----------------------------------------------------------------------------
template <int DO_RELU>
__global__ __launch_bounds__(256, 2)
void gemm128_kernel(const float* __restrict__ A, const float* __restrict__ B,
                    float* __restrict__ C, int M, int N, int Kin)
{
    constexpr int BM = 128, BN = 128, BK = 16;
    __shared__ float As[BK][BM + 4];   // +4 pad: reduce store conflicts, keep float4 align
    __shared__ float Bs[BK][BN];

    const int tid = threadIdx.x;
    const int bm = blockIdx.y * BM;
    const int bn = blockIdx.x * BN;

    const int tm8 = (tid >> 4) * 8;    // 0..120, output row group within tile
    const int tn8 = (tid & 15) * 8;    // 0..120, output col group within tile

    // A tile loads: 128 rows x 16 k, float4 along k. Each thread: 2 float4.
    const int a_row = tid >> 2;        // 0..63
    const int a_k4  = (tid & 3) * 4;   // 0,4,8,12
    // B tile loads: 16 rows x 128 cols, float4 along n. Each thread: 2 float4.
    const int b_row = tid >> 5;        // 0..7
    const int b_c4  = (tid & 31) * 4;  // 0..124

    const float* Aptr = A + (size_t)(bm + a_row) * Kin + a_k4;
    const float* Bptr = B + (size_t)b_row * N + bn + b_c4;

    float4 a0 = *(const float4*)(Aptr);
    float4 a1 = *(const float4*)(Aptr + (size_t)64 * Kin);
    float4 b0 = *(const float4*)(Bptr);
    float4 b1 = *(const float4*)(Bptr + (size_t)8 * N);

    float acc[8][8];
    #pragma unroll
    for (int i = 0; i < 8; i++)
        #pragma unroll
        for (int j = 0; j < 8; j++) acc[i][j] = 0.0f;

    const int numT = Kin / BK;
    for (int t = 0; t < numT; ++t) {
        // Stage current tile into shared memory
        As[a_k4 + 0][a_row] = a0.x;
        As[a_k4 + 1][a_row] = a0.y;
        As[a_k4 + 2][a_row] = a0.z;
        As[a_k4 + 3][a_row] = a0.w;
        As[a_k4 + 0][a_row + 64] = a1.x;
        As[a_k4 + 1][a_row + 64] = a1.y;
        As[a_k4 + 2][a_row + 64] = a1.z;
        As[a_k4 + 3][a_row + 64] = a1.w;
        *(float4*)&Bs[b_row][b_c4]     = b0;
        *(float4*)&Bs[b_row + 8][b_c4] = b1;
        __syncthreads();

        // Prefetch next tile into registers (overlaps with compute below)
        if (t + 1 < numT) {
            const float* Ap = Aptr + (size_t)(t + 1) * BK;
            a0 = *(const float4*)(Ap);
            a1 = *(const float4*)(Ap + (size_t)64 * Kin);
            const float* Bp = Bptr + (size_t)(t + 1) * BK * N;
            b0 = *(const float4*)(Bp);
            b1 = *(const float4*)(Bp + (size_t)8 * N);
        }

        #pragma unroll
        for (int kk = 0; kk < BK; kk++) {
            float4 av0 = *(const float4*)&As[kk][tm8];
            float4 av1 = *(const float4*)&As[kk][tm8 + 4];
            float4 bv0 = *(const float4*)&Bs[kk][tn8];
            float4 bv1 = *(const float4*)&Bs[kk][tn8 + 4];
            float am[8] = {av0.x, av0.y, av0.z, av0.w, av1.x, av1.y, av1.z, av1.w};
            float bb[8] = {bv0.x, bv0.y, bv0.z, bv0.w, bv1.x, bv1.y, bv1.z, bv1.w};
            #pragma unroll
            for (int i = 0; i < 8; i++)
                #pragma unroll
                for (int j = 0; j < 8; j++)
                    acc[i][j] = fmaf(am[i], bb[j], acc[i][j]);
        }
        __syncthreads();
    }

    // Epilogue: optional relu, float4 stores
    #pragma unroll
    for (int i = 0; i < 8; i++) {
        float v[8];
        #pragma unroll
        for (int j = 0; j < 8; j++) {
            float x = acc[i][j];
            v[j] = DO_RELU ? fmaxf(x, 0.0f) : x;
        }
        size_t off = (size_t)(bm + tm8 + i) * N + bn + tn8;
        float4 o0 = make_float4(v[0], v[1], v[2], v[3]);
        float4 o1 = make_float4(v[4], v[5], v[6], v[7]);
        *(float4*)&C[off]     = o0;
        *(float4*)&C[off + 4] = o1;
    }
}

// ----------------------------------------------------------------------------
// 3x3 expm (scaling & squaring + 10-term Taylor) + output assembly.
// One thread per (part p, column k). Layouts (all row-major, K=2048 cols):
//   omega[(9p + 3r + c), k]  -> A[r][c]
//   rotations[(9p + i), k]   =  E[i]
//   transf[(12p + i), k]     =  E[i]            (i < 9)
//   transf[(12p + 9 + c), k] =  translations[(3p + c), k]
// ----------------------------------------------------------------------------
__device__ __forceinline__ void mat3mul(float* __restrict__ o,
                                        const float* __restrict__ a,
                                        const float* __restrict__ b)
{
    #pragma unroll
    for (int r = 0; r < 3; r++)
        #pragma unroll
        for (int c = 0; c < 3; c++)
            o[3 * r + c] = fmaf(a[3 * r + 0], b[c],
                           fmaf(a[3 * r + 1], b[3 + c],
                                a[3 * r + 2] * b[6 + c]));
}

__global__ void expm_assemble_kernel(const float* __restrict__ omega,
                                     const float* __restrict__ trans,
                                     float* __restrict__ rotations,
                                     float* __restrict__ transf)
{
    const int idx = blockIdx.x * blockDim.x + threadIdx.x;
    const int k = idx & (KCOLS - 1);
    const int p = idx >> 11;           // KCOLS = 2^11
    if (p >= NPARTS) return;

    float A[9];
    #pragma unroll
    for (int i = 0; i < 9; i++)
        A[i] = omega[(size_t)(9 * p + i) * KCOLS + k];

    // inf-norm
    float r0 = fabsf(A[0]) + fabsf(A[1]) + fabsf(A[2]);
    float r1 = fabsf(A[3]) + fabsf(A[4]) + fabsf(A[5]);
    float r2 = fabsf(A[6]) + fabsf(A[7]) + fabsf(A[8]);
    float nrm = fmaxf(r0, fmaxf(r1, r2));

    int s = 0;
    if (nrm > 0.25f) {
        s = (int)ceilf(log2f(nrm * 4.0f));
        if (s < 0) s = 0;
        if (s > 30) s = 30;
    }
    const float sc = exp2f((float)(-s));
    #pragma unroll
    for (int i = 0; i < 9; i++) A[i] *= sc;

    // E = I + A; T = A; Taylor terms 2..10 (||A|| <= 0.25 -> remainder ~6e-15)
    float E[9], T[9], Tn[9];
    #pragma unroll
    for (int i = 0; i < 9; i++) { E[i] = A[i]; T[i] = A[i]; }
    E[0] += 1.0f; E[4] += 1.0f; E[8] += 1.0f;

    #pragma unroll
    for (int term = 2; term <= 10; term++) {
        mat3mul(Tn, T, A);
        const float inv = 1.0f / (float)term;
        #pragma unroll
        for (int i = 0; i < 9; i++) {
            T[i] = Tn[i] * inv;
            E[i] += T[i];
        }
    }

    // squarings
    for (int q = 0; q < s; q++) {
        mat3mul(Tn, E, E);
        #pragma unroll
        for (int i = 0; i < 9; i++) E[i] = Tn[i];
    }

    // Write rotations + transf rotation rows
    #pragma unroll
    for (int i = 0; i < 9; i++) {
        rotations[(size_t)(9 * p + i) * KCOLS + k] = E[i];
        transf[(size_t)(12 * p + i) * KCOLS + k]   = E[i];
    }
    // Copy translation rows into transf
    #pragma unroll
    for (int c = 0; c < 3; c++) {
        float tv = trans[(size_t)(3 * p + c) * KCOLS + k];
        transf[(size_t)(12 * p + 9 + c) * KCOLS + k] = tv;
    }
}

// ----------------------------------------------------------------------------
// Launcher. Inputs (metadata order):
//   0: x_init (128,2048)  1: Wo0 (2048,128)  2: Wo1 (2048,2048)  3: Wo2 (2048,2048)
//   4: Wo3 (1152,2048)    5: Wt0 (2048,128)  6: Wt1 (2048,2048)  7: Wt2 (2048,2048)
//   8: Wt3 (384,2048)
// Output (flattened tuple): omega | transf | rotations | translations
// ----------------------------------------------------------------------------
extern "C" void kernel_launch(void* const* d_in, const int* in_sizes, int n_in,
                              void* d_out, int out_size)
{
    const float* x   = (const float*)d_in[0];
    const float* Wo0 = (const float*)d_in[1];
    const float* Wo1 = (const float*)d_in[2];
    const float* Wo2 = (const float*)d_in[3];
    const float* Wo3 = (const float*)d_in[4];
    const float* Wt0 = (const float*)d_in[5];
    const float* Wt1 = (const float*)d_in[6];
    const float* Wt2 = (const float*)d_in[7];
    const float* Wt3 = (const float*)d_in[8];

    float* out       = (float*)d_out;
    float* omega     = out;                                       // 1152*2048
    float* transf    = omega + (size_t)OMEGA_D * KCOLS;           // 1536*2048
    float* rotations = transf + (size_t)(12 * NPARTS) * KCOLS;    // 1152*2048
    float* trans     = rotations + (size_t)OMEGA_D * KCOLS;       // 384*2048

    float *buf0, *buf1;
    cudaGetSymbolAddress((void**)&buf0, g_buf0);
    cudaGetSymbolAddress((void**)&buf1, g_buf1);

    const dim3 blk(256);
    const dim3 gHH(KCOLS / 128, HIDDEN / 128);        // (16,16)
    const dim3 gOm(KCOLS / 128, OMEGA_D / 128);       // (16,9)
    const dim3 gTr(KCOLS / 128, TRANZ_D / 128);       // (16,3)

    // omega branch
    gemm128_kernel<1><<<gHH, blk>>>(Wo0, x,    buf0, HIDDEN,  KCOLS, LATENT);
    gemm128_kernel<1><<<gHH, blk>>>(Wo1, buf0, buf1, HIDDEN,  KCOLS, HIDDEN);
    gemm128_kernel<1><<<gHH, blk>>>(Wo2, buf1, buf0, HIDDEN,  KCOLS, HIDDEN);
    gemm128_kernel<0><<<gOm, blk>>>(Wo3, buf0, omega, OMEGA_D, KCOLS, HIDDEN);

    // translation branch
    gemm128_kernel<1><<<gHH, blk>>>(Wt0, x,    buf1, HIDDEN,  KCOLS, LATENT);
    gemm128_kernel<1><<<gHH, blk>>>(Wt1, buf1, buf0, HIDDEN,  KCOLS, HIDDEN);
    gemm128_kernel<1><<<gHH, blk>>>(Wt2, buf0, buf1, HIDDEN,  KCOLS, HIDDEN);
    gemm128_kernel<0><<<gTr, blk>>>(Wt3, buf1, trans, TRANZ_D, KCOLS, HIDDEN);

    // expm + output assembly
    const int total = NPARTS * KCOLS;                 // 262144 threads
    expm_assemble_kernel<<<total / 256, 256>>>(omega, trans, rotations, transf);
}